// round 6
// baseline (speedup 1.0000x reference)
#include <cuda_runtime.h>
#include <stdint.h>

// Energy4D: 4x multi-resolution hash-grid encodings (instant-NGP style).
// L=16 levels, F=2 feats, HMAP=2^19, BASE=32, GROWTH=2 -> res_l = 32<<l.
// Level sizes: l0 dense 32768, l1 dense 262144, l>=2 hashed 524288 each.
//
// R5 -> R6:
//  (a) levels 0-7 in one kernel (touched table footprint is small: coords
//      cluster), levels 8-15 in four 2-level kernels so each kernel's hot
//      slices (~25-28 MB) are firmly L2-resident.
//  (b) x-corner pair vectorization: corners (i,i+1) differ only in 'a'.
//      When a0 is even the two entries form the aligned pair {idx&~1, idx|1}
//      (hashed: (a0+1)^X == (a0^X)^1; dense: idx1 = idx0+1, idx0 even), so
//      one 16B float4 load serves both corners; odd-a0 lanes issue one
//      predicated extra float2 load. ~25% fewer L1 wavefronts/L2 requests.
//
// Numerics must match XLA's lowering bit-for-bit (pos = u*(res-1) amplifies
// ulps by up to 2^20): x/const -> x*rn(1/const); w = rn(u*resm1) - p0_clip;
// all math via __f*_rn so --use_fast_math can't contract/approx.

constexpr unsigned HMASK = (1u << 19) - 1u;
constexpr unsigned P1 = 2654435761u;
constexpr unsigned P2 = 805459861u;

__device__ __host__ constexpr int level_offset(int l) {
    return (l == 0) ? 0 : (l == 1) ? 32768 : 294912 + (l - 2) * 524288;
}

__device__ __forceinline__ float clip01(float v) {
    return fminf(fmaxf(v, 0.0f), 1.0f);
}

template <int L0, int NLEV>
__global__ __launch_bounds__(256) void energy4d_group_kernel(
    const float4* __restrict__ coords,
    const float4* __restrict__ refc,
    const float2* __restrict__ t0,
    const float2* __restrict__ t1,
    const float2* __restrict__ t2,
    const float2* __restrict__ t3,
    float2* __restrict__ out)   // out as float2: elem = pt*64 + e*16 + l
{
    const int warp = threadIdx.x >> 5;
    const int lane = threadIdx.x & 31;
    const int e    = warp & 3;                               // encoding id
    const int pt   = (blockIdx.x * 2 + (warp >> 2)) * 32 + lane;

    const float4 c = coords[pt];
    const float4 r = refc[pt];

    // Compile-time correctly-rounded reciprocals (== XLA's folded 1/const).
    const float R180   = 1.0f / 180.0f;
    const float R360   = 1.0f / 360.0f;
    const float R20000 = 1.0f / 20000.0f;

    float nx = clip01(__fmul_rn(__fadd_rn(__fsub_rn(c.x, r.x), 90.0f),    R180));
    float ny = clip01(__fmul_rn(__fadd_rn(__fsub_rn(c.y, r.y), 180.0f),   R360));
    float nz = clip01(__fmul_rn(__fadd_rn(__fsub_rn(c.z, r.z), 11000.0f), R20000));
    float nt = clip01(__fsub_rn(c.w, r.w));
    float tsn = __fmul_rn(__fsub_rn(__fmul_rn(nt, 2.0f), 1.0f), 0.9f);

    float ux = clip01(__fmul_rn(__fadd_rn(nx,  1.0f), 0.5f));
    float uy = clip01(__fmul_rn(__fadd_rn(ny,  1.0f), 0.5f));
    float uz = clip01(__fmul_rn(__fadd_rn(nz,  1.0f), 0.5f));
    float ut = clip01(__fmul_rn(__fadd_rn(tsn, 1.0f), 0.5f));

    // encoding dim selection: e0=(x,y,z) e1=(x,y,t) e2=(y,z,t) e3=(x,z,t)
    const float ua = (e == 2) ? uy : ux;
    const float ub = (e <= 1) ? uy : uz;
    const float uc = (e == 0) ? uz : ut;
    const float2* __restrict__ tbl =
        (e == 0) ? t0 : (e == 1) ? t1 : (e == 2) ? t2 : t3;

    float2* optr = out + (size_t)pt * 64 + (size_t)e * 16 + L0;

    #pragma unroll
    for (int j = 0; j < NLEV; ++j) {
        const int   l     = L0 + j;
        const int   res   = 32 << l;
        const float resm1 = (float)(res - 1);
        const int   off   = level_offset(l);

        float pa = __fmul_rn(ua, resm1);
        float pb = __fmul_rn(ub, resm1);
        float pc = __fmul_rn(uc, resm1);
        int a0 = min(max((int)floorf(pa), 0), res - 2);
        int b0 = min(max((int)floorf(pb), 0), res - 2);
        int c0 = min(max((int)floorf(pc), 0), res - 2);
        float wa = __fsub_rn(pa, (float)a0);
        float wb = __fsub_rn(pb, (float)b0);
        float wc = __fsub_rn(pc, (float)c0);

        int idx[8];
        if (l >= 2) {
            // hashed: h = a*1 ^ b*P1 ^ c*P2 (uint32 wrap), idx = (h & HMASK) + off
            unsigned ha0 = (unsigned)a0,      ha1 = ha0 + 1u;
            unsigned hb0 = (unsigned)b0 * P1, hb1 = hb0 + P1;
            unsigned hc0 = (unsigned)c0 * P2, hc1 = hc0 + P2;
            idx[0] = (int)((ha0 ^ hb0 ^ hc0) & HMASK) + off;
            idx[1] = (int)((ha1 ^ hb0 ^ hc0) & HMASK) + off;
            idx[2] = (int)((ha0 ^ hb1 ^ hc0) & HMASK) + off;
            idx[3] = (int)((ha1 ^ hb1 ^ hc0) & HMASK) + off;
            idx[4] = (int)((ha0 ^ hb0 ^ hc1) & HMASK) + off;
            idx[5] = (int)((ha1 ^ hb0 ^ hc1) & HMASK) + off;
            idx[6] = (int)((ha0 ^ hb1 ^ hc1) & HMASK) + off;
            idx[7] = (int)((ha1 ^ hb1 ^ hc1) & HMASK) + off;
        } else {
            // dense: idx = a + res*(b + res*c) + off
            const int rr = res * res;
            int base = a0 + res * (b0 + res * c0) + off;
            idx[0] = base;
            idx[1] = base + 1;
            idx[2] = base + res;
            idx[3] = base + res + 1;
            idx[4] = base + rr;
            idx[5] = base + rr + 1;
            idx[6] = base + rr + res;
            idx[7] = base + rr + res + 1;
        }

        // Paired gathers: corners (2p, 2p+1) differ only in 'a'.
        // a0 even -> both entries live in the aligned 16B pair at idx0&~1.
        const bool aodd = (a0 & 1) != 0;
        float2 f[8];
        #pragma unroll
        for (int p = 0; p < 4; ++p) {
            const int i0 = idx[2 * p];
            const int i1 = idx[2 * p + 1];
            float4 q = __ldg((const float4*)(tbl + (i0 & ~1)));
            const bool hi = (i0 & 1) != 0;
            float2 q0 = hi ? make_float2(q.z, q.w) : make_float2(q.x, q.y);
            float2 q1 = hi ? make_float2(q.x, q.y) : make_float2(q.z, q.w);
            f[2 * p]     = q0;
            f[2 * p + 1] = aodd ? __ldg(tbl + i1) : q1;
        }

        const float oma = __fsub_rn(1.0f, wa);
        const float omb = __fsub_rn(1.0f, wb);
        const float omc = __fsub_rn(1.0f, wc);
        float accx = 0.0f, accy = 0.0f;
        #pragma unroll
        for (int i = 0; i < 8; ++i) {
            float cwa = (i & 1) ? wa : oma;
            float cwb = (i & 2) ? wb : omb;
            float cwc = (i & 4) ? wc : omc;
            float cw  = __fmul_rn(__fmul_rn(cwa, cwb), cwc);
            accx = __fadd_rn(accx, __fmul_rn(f[i].x, cw));
            accy = __fadd_rn(accy, __fmul_rn(f[i].y, cw));
        }

        optr[j] = make_float2(accx, accy);
    }
}

extern "C" void kernel_launch(void* const* d_in, const int* in_sizes, int n_in,
                              void* d_out, int out_size) {
    const int n = in_sizes[0] / 4;          // number of points (262144)
    dim3 block(256);                        // 8 warps = 2 point-groups x 4 encodings
    dim3 grid(n / 64);
    const float4* coords = (const float4*)d_in[0];
    const float4* refc   = (const float4*)d_in[1];
    const float2* t0 = (const float2*)d_in[2];
    const float2* t1 = (const float2*)d_in[3];
    const float2* t2 = (const float2*)d_in[4];
    const float2* t3 = (const float2*)d_in[5];
    float2* out = (float2*)d_out;

    energy4d_group_kernel<0, 8><<<grid, block>>>(coords, refc, t0, t1, t2, t3, out);
    energy4d_group_kernel<8, 2><<<grid, block>>>(coords, refc, t0, t1, t2, t3, out);
    energy4d_group_kernel<10, 2><<<grid, block>>>(coords, refc, t0, t1, t2, t3, out);
    energy4d_group_kernel<12, 2><<<grid, block>>>(coords, refc, t0, t1, t2, t3, out);
    energy4d_group_kernel<14, 2><<<grid, block>>>(coords, refc, t0, t1, t2, t3, out);
}

// round 7
// speedup vs baseline: 1.0353x; 1.0353x over previous
#include <cuda_runtime.h>
#include <stdint.h>

// Energy4D: 4x multi-resolution hash-grid encodings (instant-NGP style).
// L=16 levels, F=2 feats, HMAP=2^19, BASE=32, GROWTH=2 -> res_l = 32<<l.
// Level sizes: l0 dense 32768, l1 dense 262144, l>=2 hashed 524288 each.
//
// R6 -> R7: revert to R5's 4-kernel x 4-level structure (extra splits only
// added launch tails; DRAM wasn't binding). Keep ONLY the x-corner pairing:
// corners (2p, 2p+1) differ in 'a' alone; for even a0 both entries are the
// aligned 16B pair {idx&~1, idx|1} (hashed: (a0+1)^X == (a0^X)^1; dense:
// idx1 = idx0+1). One float4 load serves both corners; odd-a0 lanes issue a
// predicated extra float2 load. ~25% fewer L1 wavefronts / L2 requests where
// R5 measured L1=76%/L2=78.5% (the binding wall).
//
// Numerics must match XLA's lowering bit-for-bit (pos = u*(res-1) amplifies
// ulps by up to 2^20): x/const -> x*rn(1/const); w = rn(u*resm1) - p0_clip;
// all math via __f*_rn so --use_fast_math can't contract/approx.

constexpr unsigned HMASK = (1u << 19) - 1u;
constexpr unsigned P1 = 2654435761u;
constexpr unsigned P2 = 805459861u;

__device__ __host__ constexpr int level_offset(int l) {
    return (l == 0) ? 0 : (l == 1) ? 32768 : 294912 + (l - 2) * 524288;
}

__device__ __forceinline__ float clip01(float v) {
    return fminf(fmaxf(v, 0.0f), 1.0f);
}

template <int L0, int NLEV>
__global__ __launch_bounds__(256) void energy4d_group_kernel(
    const float4* __restrict__ coords,
    const float4* __restrict__ refc,
    const float2* __restrict__ t0,
    const float2* __restrict__ t1,
    const float2* __restrict__ t2,
    const float2* __restrict__ t3,
    float2* __restrict__ out)   // out as float2: elem = pt*64 + e*16 + l
{
    const int warp = threadIdx.x >> 5;
    const int lane = threadIdx.x & 31;
    const int e    = warp & 3;                               // encoding id
    const int pt   = (blockIdx.x * 2 + (warp >> 2)) * 32 + lane;

    const float4 c = coords[pt];
    const float4 r = refc[pt];

    // Compile-time correctly-rounded reciprocals (== XLA's folded 1/const).
    const float R180   = 1.0f / 180.0f;
    const float R360   = 1.0f / 360.0f;
    const float R20000 = 1.0f / 20000.0f;

    float nx = clip01(__fmul_rn(__fadd_rn(__fsub_rn(c.x, r.x), 90.0f),    R180));
    float ny = clip01(__fmul_rn(__fadd_rn(__fsub_rn(c.y, r.y), 180.0f),   R360));
    float nz = clip01(__fmul_rn(__fadd_rn(__fsub_rn(c.z, r.z), 11000.0f), R20000));
    float nt = clip01(__fsub_rn(c.w, r.w));
    float tsn = __fmul_rn(__fsub_rn(__fmul_rn(nt, 2.0f), 1.0f), 0.9f);

    float ux = clip01(__fmul_rn(__fadd_rn(nx,  1.0f), 0.5f));
    float uy = clip01(__fmul_rn(__fadd_rn(ny,  1.0f), 0.5f));
    float uz = clip01(__fmul_rn(__fadd_rn(nz,  1.0f), 0.5f));
    float ut = clip01(__fmul_rn(__fadd_rn(tsn, 1.0f), 0.5f));

    // encoding dim selection: e0=(x,y,z) e1=(x,y,t) e2=(y,z,t) e3=(x,z,t)
    const float ua = (e == 2) ? uy : ux;
    const float ub = (e <= 1) ? uy : uz;
    const float uc = (e == 0) ? uz : ut;
    const float2* __restrict__ tbl =
        (e == 0) ? t0 : (e == 1) ? t1 : (e == 2) ? t2 : t3;

    float2* optr = out + (size_t)pt * 64 + (size_t)e * 16 + L0;

    #pragma unroll
    for (int j = 0; j < NLEV; ++j) {
        const int   l     = L0 + j;
        const int   res   = 32 << l;
        const float resm1 = (float)(res - 1);
        const int   off   = level_offset(l);

        float pa = __fmul_rn(ua, resm1);
        float pb = __fmul_rn(ub, resm1);
        float pc = __fmul_rn(uc, resm1);
        int a0 = min(max((int)floorf(pa), 0), res - 2);
        int b0 = min(max((int)floorf(pb), 0), res - 2);
        int c0 = min(max((int)floorf(pc), 0), res - 2);
        float wa = __fsub_rn(pa, (float)a0);
        float wb = __fsub_rn(pb, (float)b0);
        float wc = __fsub_rn(pc, (float)c0);

        int idx[8];
        if (l >= 2) {
            // hashed: h = a*1 ^ b*P1 ^ c*P2 (uint32 wrap), idx = (h & HMASK) + off
            unsigned ha0 = (unsigned)a0,      ha1 = ha0 + 1u;
            unsigned hb0 = (unsigned)b0 * P1, hb1 = hb0 + P1;
            unsigned hc0 = (unsigned)c0 * P2, hc1 = hc0 + P2;
            idx[0] = (int)((ha0 ^ hb0 ^ hc0) & HMASK) + off;
            idx[1] = (int)((ha1 ^ hb0 ^ hc0) & HMASK) + off;
            idx[2] = (int)((ha0 ^ hb1 ^ hc0) & HMASK) + off;
            idx[3] = (int)((ha1 ^ hb1 ^ hc0) & HMASK) + off;
            idx[4] = (int)((ha0 ^ hb0 ^ hc1) & HMASK) + off;
            idx[5] = (int)((ha1 ^ hb0 ^ hc1) & HMASK) + off;
            idx[6] = (int)((ha0 ^ hb1 ^ hc1) & HMASK) + off;
            idx[7] = (int)((ha1 ^ hb1 ^ hc1) & HMASK) + off;
        } else {
            // dense: idx = a + res*(b + res*c) + off
            const int rr = res * res;
            int base = a0 + res * (b0 + res * c0) + off;
            idx[0] = base;
            idx[1] = base + 1;
            idx[2] = base + res;
            idx[3] = base + res + 1;
            idx[4] = base + rr;
            idx[5] = base + rr + 1;
            idx[6] = base + rr + res;
            idx[7] = base + rr + res + 1;
        }

        // Paired gathers: corners (2p, 2p+1) differ only in 'a'.
        // a0 even -> both entries live in the aligned 16B pair at idx0&~1.
        const bool aodd = (a0 & 1) != 0;
        float2 f[8];
        #pragma unroll
        for (int p = 0; p < 4; ++p) {
            const int i0 = idx[2 * p];
            const int i1 = idx[2 * p + 1];
            float4 q = __ldg((const float4*)(tbl + (i0 & ~1)));
            const bool hi = (i0 & 1) != 0;
            float2 q0 = hi ? make_float2(q.z, q.w) : make_float2(q.x, q.y);
            float2 q1 = hi ? make_float2(q.x, q.y) : make_float2(q.z, q.w);
            f[2 * p]     = q0;
            f[2 * p + 1] = aodd ? __ldg(tbl + i1) : q1;
        }

        const float oma = __fsub_rn(1.0f, wa);
        const float omb = __fsub_rn(1.0f, wb);
        const float omc = __fsub_rn(1.0f, wc);
        float accx = 0.0f, accy = 0.0f;
        #pragma unroll
        for (int i = 0; i < 8; ++i) {
            float cwa = (i & 1) ? wa : oma;
            float cwb = (i & 2) ? wb : omb;
            float cwc = (i & 4) ? wc : omc;
            float cw  = __fmul_rn(__fmul_rn(cwa, cwb), cwc);
            accx = __fadd_rn(accx, __fmul_rn(f[i].x, cw));
            accy = __fadd_rn(accy, __fmul_rn(f[i].y, cw));
        }

        optr[j] = make_float2(accx, accy);
    }
}

extern "C" void kernel_launch(void* const* d_in, const int* in_sizes, int n_in,
                              void* d_out, int out_size) {
    const int n = in_sizes[0] / 4;          // number of points (262144)
    dim3 block(256);                        // 8 warps = 2 point-groups x 4 encodings
    dim3 grid(n / 64);
    const float4* coords = (const float4*)d_in[0];
    const float4* refc   = (const float4*)d_in[1];
    const float2* t0 = (const float2*)d_in[2];
    const float2* t1 = (const float2*)d_in[3];
    const float2* t2 = (const float2*)d_in[4];
    const float2* t3 = (const float2*)d_in[5];
    float2* out = (float2*)d_out;

    energy4d_group_kernel<0,  4><<<grid, block>>>(coords, refc, t0, t1, t2, t3, out);
    energy4d_group_kernel<4,  4><<<grid, block>>>(coords, refc, t0, t1, t2, t3, out);
    energy4d_group_kernel<8,  4><<<grid, block>>>(coords, refc, t0, t1, t2, t3, out);
    energy4d_group_kernel<12, 4><<<grid, block>>>(coords, refc, t0, t1, t2, t3, out);
}

// round 9
// speedup vs baseline: 1.3605x; 1.3142x over previous
#include <cuda_runtime.h>
#include <stdint.h>

// Energy4D: 4x multi-resolution hash-grid encodings (instant-NGP style).
// L=16 levels, F=2 feats, HMAP=2^19, BASE=32, GROWTH=2 -> res_l = 32<<l.
// Level sizes: l0 dense 32768, l1 dense 262144, l>=2 hashed 524288 each.
//
// R8 -> R9: ptxas rejects bare .L2::evict_last on ld.v2 — use the legal
// form: createpolicy.fractional.L2::evict_last + ld.global.nc.L2::cache_hint.
// Same theory as R8: R5's fine kernels moved ~390 MB DRAM for a 64 MB table
// working set (L2 thrash). Keep tables L2-resident (evict-last gathers),
// stream the output (st.global.cs, coalesced 2x16B per thread).
// Structure: R5's proven 4 kernels x 4 levels.
//
// Numerics must match XLA's lowering bit-for-bit (pos = u*(res-1) amplifies
// ulps by up to 2^20): x/const -> x*rn(1/const); w = rn(u*resm1) - p0_clip;
// all math via __f*_rn so --use_fast_math can't contract/approx.

constexpr unsigned HMASK = (1u << 19) - 1u;
constexpr unsigned P1 = 2654435761u;
constexpr unsigned P2 = 805459861u;

__device__ __host__ constexpr int level_offset(int l) {
    return (l == 0) ? 0 : (l == 1) ? 32768 : 294912 + (l - 2) * 524288;
}

__device__ __forceinline__ float clip01(float v) {
    return fminf(fmaxf(v, 0.0f), 1.0f);
}

// Table gather: non-coherent load with L2 evict-last cache hint.
__device__ __forceinline__ float2 ldg_tbl(const float2* p, uint64_t pol) {
    float2 v;
    asm("ld.global.nc.L2::cache_hint.v2.f32 {%0,%1}, [%2], %3;"
        : "=f"(v.x), "=f"(v.y) : "l"(p), "l"(pol));
    return v;
}

// Streaming 16B store (evict-first): don't let the write stream evict tables.
__device__ __forceinline__ void st_cs4(float4* p, float4 v) {
    asm volatile("st.global.cs.v4.f32 [%0], {%1,%2,%3,%4};"
                 :: "l"(p), "f"(v.x), "f"(v.y), "f"(v.z), "f"(v.w) : "memory");
}

template <int L0, int NLEV>
__global__ __launch_bounds__(256) void energy4d_group_kernel(
    const float4* __restrict__ coords,
    const float4* __restrict__ refc,
    const float2* __restrict__ t0,
    const float2* __restrict__ t1,
    const float2* __restrict__ t2,
    const float2* __restrict__ t3,
    float2* __restrict__ out)   // out as float2: elem = pt*64 + e*16 + l
{
    const int warp = threadIdx.x >> 5;
    const int lane = threadIdx.x & 31;
    const int e    = warp & 3;                               // encoding id
    const int pt   = (blockIdx.x * 2 + (warp >> 2)) * 32 + lane;

    // L2 evict-last policy for all table gathers (uniform per thread).
    uint64_t pol;
    asm("createpolicy.fractional.L2::evict_last.b64 %0, 1.0;" : "=l"(pol));

    const float4 c = coords[pt];
    const float4 r = refc[pt];

    // Compile-time correctly-rounded reciprocals (== XLA's folded 1/const).
    const float R180   = 1.0f / 180.0f;
    const float R360   = 1.0f / 360.0f;
    const float R20000 = 1.0f / 20000.0f;

    float nx = clip01(__fmul_rn(__fadd_rn(__fsub_rn(c.x, r.x), 90.0f),    R180));
    float ny = clip01(__fmul_rn(__fadd_rn(__fsub_rn(c.y, r.y), 180.0f),   R360));
    float nz = clip01(__fmul_rn(__fadd_rn(__fsub_rn(c.z, r.z), 11000.0f), R20000));
    float nt = clip01(__fsub_rn(c.w, r.w));
    float tsn = __fmul_rn(__fsub_rn(__fmul_rn(nt, 2.0f), 1.0f), 0.9f);

    float ux = clip01(__fmul_rn(__fadd_rn(nx,  1.0f), 0.5f));
    float uy = clip01(__fmul_rn(__fadd_rn(ny,  1.0f), 0.5f));
    float uz = clip01(__fmul_rn(__fadd_rn(nz,  1.0f), 0.5f));
    float ut = clip01(__fmul_rn(__fadd_rn(tsn, 1.0f), 0.5f));

    // encoding dim selection: e0=(x,y,z) e1=(x,y,t) e2=(y,z,t) e3=(x,z,t)
    const float ua = (e == 2) ? uy : ux;
    const float ub = (e <= 1) ? uy : uz;
    const float uc = (e == 0) ? uz : ut;
    const float2* __restrict__ tbl =
        (e == 0) ? t0 : (e == 1) ? t1 : (e == 2) ? t2 : t3;

    float2 acc[NLEV];

    #pragma unroll
    for (int j = 0; j < NLEV; ++j) {
        const int   l     = L0 + j;
        const int   res   = 32 << l;
        const float resm1 = (float)(res - 1);
        const int   off   = level_offset(l);

        float pa = __fmul_rn(ua, resm1);
        float pb = __fmul_rn(ub, resm1);
        float pc = __fmul_rn(uc, resm1);
        int a0 = min(max((int)floorf(pa), 0), res - 2);
        int b0 = min(max((int)floorf(pb), 0), res - 2);
        int c0 = min(max((int)floorf(pc), 0), res - 2);
        float wa = __fsub_rn(pa, (float)a0);
        float wb = __fsub_rn(pb, (float)b0);
        float wc = __fsub_rn(pc, (float)c0);

        int idx[8];
        if (l >= 2) {
            // hashed: h = a*1 ^ b*P1 ^ c*P2 (uint32 wrap), idx = (h & HMASK) + off
            unsigned ha0 = (unsigned)a0,      ha1 = ha0 + 1u;
            unsigned hb0 = (unsigned)b0 * P1, hb1 = hb0 + P1;
            unsigned hc0 = (unsigned)c0 * P2, hc1 = hc0 + P2;
            idx[0] = (int)((ha0 ^ hb0 ^ hc0) & HMASK) + off;
            idx[1] = (int)((ha1 ^ hb0 ^ hc0) & HMASK) + off;
            idx[2] = (int)((ha0 ^ hb1 ^ hc0) & HMASK) + off;
            idx[3] = (int)((ha1 ^ hb1 ^ hc0) & HMASK) + off;
            idx[4] = (int)((ha0 ^ hb0 ^ hc1) & HMASK) + off;
            idx[5] = (int)((ha1 ^ hb0 ^ hc1) & HMASK) + off;
            idx[6] = (int)((ha0 ^ hb1 ^ hc1) & HMASK) + off;
            idx[7] = (int)((ha1 ^ hb1 ^ hc1) & HMASK) + off;
        } else {
            // dense: idx = a + res*(b + res*c) + off
            const int rr = res * res;
            int base = a0 + res * (b0 + res * c0) + off;
            idx[0] = base;
            idx[1] = base + 1;
            idx[2] = base + res;
            idx[3] = base + res + 1;
            idx[4] = base + rr;
            idx[5] = base + rr + 1;
            idx[6] = base + rr + res;
            idx[7] = base + rr + res + 1;
        }

        // 8 independent gathers (MLP=8 per level), L2 evict-last
        float2 f[8];
        #pragma unroll
        for (int i = 0; i < 8; ++i) f[i] = ldg_tbl(&tbl[idx[i]], pol);

        const float oma = __fsub_rn(1.0f, wa);
        const float omb = __fsub_rn(1.0f, wb);
        const float omc = __fsub_rn(1.0f, wc);
        float accx = 0.0f, accy = 0.0f;
        #pragma unroll
        for (int i = 0; i < 8; ++i) {
            float cwa = (i & 1) ? wa : oma;
            float cwb = (i & 2) ? wb : omb;
            float cwc = (i & 4) ? wc : omc;
            float cw  = __fmul_rn(__fmul_rn(cwa, cwb), cwc);
            accx = __fadd_rn(accx, __fmul_rn(f[i].x, cw));
            accy = __fadd_rn(accy, __fmul_rn(f[i].y, cw));
        }
        acc[j] = make_float2(accx, accy);
    }

    // Coalesced streaming stores: NLEV float2 -> NLEV/2 x 16B st.cs
    float2* optr = out + (size_t)pt * 64 + (size_t)e * 16 + L0;
    #pragma unroll
    for (int j = 0; j < NLEV; j += 2) {
        st_cs4((float4*)(optr + j),
               make_float4(acc[j].x, acc[j].y, acc[j + 1].x, acc[j + 1].y));
    }
}

extern "C" void kernel_launch(void* const* d_in, const int* in_sizes, int n_in,
                              void* d_out, int out_size) {
    const int n = in_sizes[0] / 4;          // number of points (262144)
    dim3 block(256);                        // 8 warps = 2 point-groups x 4 encodings
    dim3 grid(n / 64);
    const float4* coords = (const float4*)d_in[0];
    const float4* refc   = (const float4*)d_in[1];
    const float2* t0 = (const float2*)d_in[2];
    const float2* t1 = (const float2*)d_in[3];
    const float2* t2 = (const float2*)d_in[4];
    const float2* t3 = (const float2*)d_in[5];
    float2* out = (float2*)d_out;

    energy4d_group_kernel<0,  4><<<grid, block>>>(coords, refc, t0, t1, t2, t3, out);
    energy4d_group_kernel<4,  4><<<grid, block>>>(coords, refc, t0, t1, t2, t3, out);
    energy4d_group_kernel<8,  4><<<grid, block>>>(coords, refc, t0, t1, t2, t3, out);
    energy4d_group_kernel<12, 4><<<grid, block>>>(coords, refc, t0, t1, t2, t3, out);
}